// round 5
// baseline (speedup 1.0000x reference)
#include <cuda_runtime.h>
#include <cuda_bf16.h>
#include <cstdint>
#include <math.h>

// Problem constants
#define BB 32
#define SS 2048
#define HH 1024

// Tiling
#define BM 128
#define BN 256
#define KC 32
#define NTILES (HH / BN)      // 4
#define STILES (SS / BM)      // 16
#define NCHUNK (HH / KC)      // 32
#define THREADS 512

// SMEM (u32 units): A hi/lo: 2 stages x 128 rows x 17 ; B hi/lo: 2 stages x 256 x 17
#define A_STAGE_U32 (128 * 17)          // 2176
#define B_STAGE_U32 (256 * 17)          // 4352
#define SMEM_U32 (2*A_STAGE_U32 + 2*A_STAGE_U32 + 2*B_STAGE_U32 + 2*B_STAGE_U32) // 26112
#define SMEM_BYTES (SMEM_U32 * 4)       // 104448

// Device scratch (static: no allocations allowed)
__device__ uint32_t g_WkHi[HH * (HH / 2)];   // [n][h/2] packed bf16x2 (hi parts)
__device__ uint32_t g_WkLo[HH * (HH / 2)];   // lo parts
__device__ float    g_q[BB * HH];            // q = hidden @ Wq^T
__device__ float    g_partial[BB * SS * NTILES];

__device__ __forceinline__ uint32_t pack_bf2(__nv_bfloat16 a, __nv_bfloat16 b) {
    __nv_bfloat162 t = __halves2bfloat162(a, b);  // .x = a (low), .y = b (high)
    return *reinterpret_cast<uint32_t*>(&t);
}

__device__ __forceinline__ void split_f32(float f, __nv_bfloat16& h, __nv_bfloat16& l) {
    h = __float2bfloat16_rn(f);
    l = __float2bfloat16_rn(f - __bfloat162float(h));
}

__device__ __forceinline__ void mma16816(float* d, const uint32_t* a, const uint32_t* b) {
    asm volatile(
        "mma.sync.aligned.m16n8k16.row.col.f32.bf16.bf16.f32 "
        "{%0,%1,%2,%3}, {%4,%5,%6,%7}, {%8,%9}, {%0,%1,%2,%3};\n"
        : "+f"(d[0]), "+f"(d[1]), "+f"(d[2]), "+f"(d[3])
        : "r"(a[0]), "r"(a[1]), "r"(a[2]), "r"(a[3]), "r"(b[0]), "r"(b[1]));
}

// ---------------------------------------------------------------------------
// Prep: split Wk into bf16 hi/lo, pair-packed along h
// ---------------------------------------------------------------------------
__global__ void k_split_wk(const float* __restrict__ Wk) {
    int i = blockIdx.x * blockDim.x + threadIdx.x;   // pair index
    if (i >= HH * HH / 2) return;
    int n = i >> 9;          // row
    int p = i & 511;         // pair within row
    float f0 = Wk[(size_t)n * HH + 2 * p];
    float f1 = Wk[(size_t)n * HH + 2 * p + 1];
    __nv_bfloat16 h0, l0, h1, l1;
    split_f32(f0, h0, l0);
    split_f32(f1, h1, l1);
    g_WkHi[i] = pack_bf2(h0, h1);
    g_WkLo[i] = pack_bf2(l0, l1);
}

// ---------------------------------------------------------------------------
// Prep: q[b][n] = sum_h hidden[b][h] * Wq[n][h]   (fp32, exact-ish)
// ---------------------------------------------------------------------------
__global__ void k_query(const float* __restrict__ hidden, const float* __restrict__ Wq) {
    int idx = blockIdx.x * blockDim.x + threadIdx.x;  // 0..32767
    if (idx >= BB * HH) return;
    int b = idx >> 10;
    int n = idx & 1023;
    const float* hp = hidden + (size_t)b * HH;
    const float* wp = Wq + (size_t)n * HH;
    float a0 = 0.f, a1 = 0.f, a2 = 0.f, a3 = 0.f;
    #pragma unroll 4
    for (int h = 0; h < HH; h += 4) {
        a0 = fmaf(hp[h + 0], wp[h + 0], a0);
        a1 = fmaf(hp[h + 1], wp[h + 1], a1);
        a2 = fmaf(hp[h + 2], wp[h + 2], a2);
        a3 = fmaf(hp[h + 3], wp[h + 3], a3);
    }
    g_q[idx] = (a0 + a1) + (a2 + a3);
}

// ---------------------------------------------------------------------------
// Main fused kernel: keys-GEMM (bf16x3) + tanh(q+keys)*v row reduction
// Grid: (NTILES, STILES, BB); ntile fastest-varying for L2 reuse of E tiles.
// ---------------------------------------------------------------------------
__global__ __launch_bounds__(THREADS, 1)
void k_attn(const float* __restrict__ enc, const float* __restrict__ v) {
    extern __shared__ uint32_t smem[];
    __shared__ float s_q[BN];
    __shared__ float s_v[BN];
    __shared__ float s_red[4 * BM];   // per warp_n partial row sums

    const int tid = threadIdx.x;
    const int ntile = blockIdx.x;
    const int stile = blockIdx.y;
    const int b = blockIdx.z;
    const int n0 = ntile * BN;
    const float* etile = enc + ((size_t)b * SS + (size_t)stile * BM) * HH;

    if (tid < BN) {
        s_q[tid] = g_q[b * HH + n0 + tid];
        s_v[tid] = v[n0 + tid];
    }

    uint32_t* sAh = smem;
    uint32_t* sAl = smem + 2 * A_STAGE_U32;
    uint32_t* sBh = smem + 4 * A_STAGE_U32;
    uint32_t* sBl = smem + 4 * A_STAGE_U32 + 2 * B_STAGE_U32;

    // staging registers for global->smem
    float4 eS[2];
    uint4  whS[2], wlS[2];

    const int ec4  = tid & 7;        // float4 column within E chunk row
    const int wq4  = tid & 3;        // uint4 column within Wk chunk row

    const int lane = tid & 31;
    const int wid  = tid >> 5;
    const int g    = lane >> 2;
    const int tig  = lane & 3;
    const int wm   = wid & 3;        // 4 warps along M (rows of 32)
    const int wn   = wid >> 2;       // 4 warps along N (cols of 64)

    float C[2][8][4];
    #pragma unroll
    for (int mt = 0; mt < 2; ++mt)
        #pragma unroll
        for (int nt = 0; nt < 8; ++nt)
            #pragma unroll
            for (int r = 0; r < 4; ++r) C[mt][nt][r] = 0.f;

    // ---- lambdas ----
    auto load_g = [&](int kc) {
        int kpos = kc * KC;
        #pragma unroll
        for (int k = 0; k < 2; ++k) {
            int row = (tid >> 3) + k * 64;
            eS[k] = *reinterpret_cast<const float4*>(etile + (size_t)row * HH + kpos + ec4 * 4);
        }
        int pc = kc * (KC / 2);
        #pragma unroll
        for (int k = 0; k < 2; ++k) {
            int row = n0 + (tid >> 2) + k * 128;
            whS[k] = *reinterpret_cast<const uint4*>(&g_WkHi[(size_t)row * (HH / 2) + pc + wq4 * 4]);
            wlS[k] = *reinterpret_cast<const uint4*>(&g_WkLo[(size_t)row * (HH / 2) + pc + wq4 * 4]);
        }
    };

    auto store_s = [&](int st) {
        uint32_t* ah = sAh + st * A_STAGE_U32;
        uint32_t* al = sAl + st * A_STAGE_U32;
        #pragma unroll
        for (int k = 0; k < 2; ++k) {
            int row = (tid >> 3) + k * 64;
            float4 f = eS[k];
            __nv_bfloat16 h0, l0, h1, l1, h2, l2, h3, l3;
            split_f32(f.x, h0, l0); split_f32(f.y, h1, l1);
            split_f32(f.z, h2, l2); split_f32(f.w, h3, l3);
            ah[row * 17 + ec4 * 2 + 0] = pack_bf2(h0, h1);
            ah[row * 17 + ec4 * 2 + 1] = pack_bf2(h2, h3);
            al[row * 17 + ec4 * 2 + 0] = pack_bf2(l0, l1);
            al[row * 17 + ec4 * 2 + 1] = pack_bf2(l2, l3);
        }
        uint32_t* bh = sBh + st * B_STAGE_U32;
        uint32_t* bl = sBl + st * B_STAGE_U32;
        #pragma unroll
        for (int k = 0; k < 2; ++k) {
            int row = (tid >> 2) + k * 128;
            bh[row * 17 + wq4 * 4 + 0] = whS[k].x;
            bh[row * 17 + wq4 * 4 + 1] = whS[k].y;
            bh[row * 17 + wq4 * 4 + 2] = whS[k].z;
            bh[row * 17 + wq4 * 4 + 3] = whS[k].w;
            bl[row * 17 + wq4 * 4 + 0] = wlS[k].x;
            bl[row * 17 + wq4 * 4 + 1] = wlS[k].y;
            bl[row * 17 + wq4 * 4 + 2] = wlS[k].z;
            bl[row * 17 + wq4 * 4 + 3] = wlS[k].w;
        }
    };

    // ---- mainloop: double-buffered ----
    load_g(0);
    store_s(0);
    __syncthreads();

    for (int kc = 0; kc < NCHUNK; ++kc) {
        const int cur = kc & 1;
        if (kc + 1 < NCHUNK) load_g(kc + 1);

        uint32_t* ah = sAh + cur * A_STAGE_U32;
        uint32_t* al = sAl + cur * A_STAGE_U32;
        uint32_t* bh = sBh + cur * B_STAGE_U32;
        uint32_t* bl = sBl + cur * B_STAGE_U32;

        #pragma unroll
        for (int ks = 0; ks < 2; ++ks) {
            const int kp = ks * 8 + tig;
            uint32_t Ah[2][4], Al[2][4];
            #pragma unroll
            for (int mt = 0; mt < 2; ++mt) {
                int r0 = wm * 32 + mt * 16 + g;
                Ah[mt][0] = ah[r0 * 17 + kp];
                Ah[mt][1] = ah[(r0 + 8) * 17 + kp];
                Ah[mt][2] = ah[r0 * 17 + kp + 4];
                Ah[mt][3] = ah[(r0 + 8) * 17 + kp + 4];
                Al[mt][0] = al[r0 * 17 + kp];
                Al[mt][1] = al[(r0 + 8) * 17 + kp];
                Al[mt][2] = al[r0 * 17 + kp + 4];
                Al[mt][3] = al[(r0 + 8) * 17 + kp + 4];
            }
            #pragma unroll
            for (int nt = 0; nt < 8; ++nt) {
                int br = wn * 64 + nt * 8 + g;
                uint32_t Bh[2] = { bh[br * 17 + kp], bh[br * 17 + kp + 4] };
                uint32_t Bl[2] = { bl[br * 17 + kp], bl[br * 17 + kp + 4] };
                #pragma unroll
                for (int mt = 0; mt < 2; ++mt) {
                    mma16816(C[mt][nt], Ah[mt], Bh);   // hi*hi
                    mma16816(C[mt][nt], Al[mt], Bh);   // lo*hi
                    mma16816(C[mt][nt], Ah[mt], Bl);   // hi*lo
                }
            }
        }

        if (kc + 1 < NCHUNK) store_s(cur ^ 1);
        __syncthreads();
    }

    // ---- epilogue: tanh(q + keys) * v, reduce over this CTA's BN columns ----
    float rs[2][2] = {{0.f, 0.f}, {0.f, 0.f}};
    #pragma unroll
    for (int mt = 0; mt < 2; ++mt)
        #pragma unroll
        for (int nt = 0; nt < 8; ++nt)
            #pragma unroll
            for (int r = 0; r < 4; ++r) {
                int col = wn * 64 + nt * 8 + tig * 2 + (r & 1);
                float e = tanhf(s_q[col] + C[mt][nt][r]) * s_v[col];
                rs[mt][r >> 1] += e;
            }

    #pragma unroll
    for (int mt = 0; mt < 2; ++mt)
        #pragma unroll
        for (int hh = 0; hh < 2; ++hh) {
            float x = rs[mt][hh];
            x += __shfl_xor_sync(0xffffffffu, x, 1);
            x += __shfl_xor_sync(0xffffffffu, x, 2);
            if (tig == 0) {
                int row = wm * 32 + mt * 16 + hh * 8 + g;
                s_red[wn * BM + row] = x;   // deterministic: one writer per slot
            }
        }
    __syncthreads();

    if (tid < BM) {
        float t = s_red[tid] + s_red[BM + tid] + s_red[2 * BM + tid] + s_red[3 * BM + tid];
        size_t grow = (size_t)b * SS + (size_t)stile * BM + tid;
        g_partial[grow * NTILES + ntile] = t;
    }
}

// ---------------------------------------------------------------------------
// Masked softmax over S per batch.
// NOTE: lengths is int32 (JAX silently downcasts jnp.int64 -> int32 without
// x64 mode). Reading it as int64 was the NaN bug: OOB reads for b >= 16
// produced len=0 -> fully-masked row -> exp(-inf - -inf) = NaN.
// ---------------------------------------------------------------------------
__global__ void k_softmax(const int* __restrict__ lengths, float* __restrict__ out) {
    const int b = blockIdx.x;
    const int tid = threadIdx.x;      // 256 threads
    const int lane = tid & 31, wid = tid >> 5;
    int len = lengths[b];
    if (len < 1) len = 1;             // defensive: avoid fully-masked NaN

    float a[8];
    float mx = -INFINITY;
    #pragma unroll
    for (int i = 0; i < 8; ++i) {
        int s = tid + i * 256;
        const float* p = &g_partial[((size_t)b * SS + s) * NTILES];
        float vv = (p[0] + p[1]) + (p[2] + p[3]);
        if (s >= len) vv = -INFINITY;
        a[i] = vv;
        mx = fmaxf(mx, vv);
    }

    __shared__ float smax[8];
    __shared__ float ssum[8];

    #pragma unroll
    for (int o = 16; o > 0; o >>= 1) mx = fmaxf(mx, __shfl_xor_sync(0xffffffffu, mx, o));
    if (lane == 0) smax[wid] = mx;
    __syncthreads();
    if (wid == 0) {
        float t = (lane < 8) ? smax[lane] : -INFINITY;
        #pragma unroll
        for (int o = 4; o > 0; o >>= 1) t = fmaxf(t, __shfl_xor_sync(0xffffffffu, t, o));
        if (lane == 0) smax[0] = t;
    }
    __syncthreads();
    mx = smax[0];

    float sum = 0.f;
    #pragma unroll
    for (int i = 0; i < 8; ++i) {
        float e = expf(a[i] - mx);   // exp(-inf - mx) = 0 for masked
        a[i] = e;
        sum += e;
    }
    #pragma unroll
    for (int o = 16; o > 0; o >>= 1) sum += __shfl_xor_sync(0xffffffffu, sum, o);
    if (lane == 0) ssum[wid] = sum;
    __syncthreads();
    if (wid == 0) {
        float t = (lane < 8) ? ssum[lane] : 0.f;
        #pragma unroll
        for (int o = 4; o > 0; o >>= 1) t += __shfl_xor_sync(0xffffffffu, t, o);
        if (lane == 0) ssum[0] = t;
    }
    __syncthreads();
    const float inv = 1.f / ssum[0];

    #pragma unroll
    for (int i = 0; i < 8; ++i) {
        int s = tid + i * 256;
        out[(size_t)b * SS + s] = a[i] * inv;
    }
}

// ---------------------------------------------------------------------------
extern "C" void kernel_launch(void* const* d_in, const int* in_sizes, int n_in,
                              void* d_out, int out_size) {
    const float*      hidden  = (const float*)d_in[0];
    const float*      enc     = (const float*)d_in[1];
    const int*        lengths = (const int*)d_in[2];    // int32 (JAX downcast)
    const float*      Wq      = (const float*)d_in[3];
    const float*      Wk      = (const float*)d_in[4];
    const float*      v       = (const float*)d_in[5];
    float* out = (float*)d_out;

    cudaFuncSetAttribute(k_attn, cudaFuncAttributeMaxDynamicSharedMemorySize, SMEM_BYTES);

    k_split_wk<<<(HH * HH / 2 + 255) / 256, 256>>>(Wk);
    k_query<<<(BB * HH + 255) / 256, 256>>>(hidden, Wq);

    dim3 grid(NTILES, STILES, BB);
    k_attn<<<grid, THREADS, SMEM_BYTES>>>(enc, v);

    k_softmax<<<BB, 256>>>(lengths, out);
}

// round 7
// speedup vs baseline: 1.0813x; 1.0813x over previous
#include <cuda_runtime.h>
#include <cuda_bf16.h>
#include <cstdint>
#include <math.h>

// Problem constants
#define BB 32
#define SS 2048
#define HH 1024

// Tiling
#define BM 128
#define BN 256
#define KC 32                   // K elements per chunk (16 u32 of bf16x2)
#define NTILES (HH / BN)        // 4
#define STILES (SS / BM)        // 16
#define NCHUNK (HH / KC)        // 32
#define THREADS 512
#define NSTAGE 3

// Per-stage smem layout (bytes). Rows padded 64B->80B (20 u32): 16B-aligned
// for cp.async and conflict-free for fragment LDS (banks (r*20+kp)%32 cover all 32).
#define ROW_U32 20
#define OFF_AH 0
#define OFF_AL (128 * 80)                 // 10240
#define OFF_BH (2 * 128 * 80)             // 20480
#define OFF_BL (2 * 128 * 80 + 256 * 80)  // 40960
#define STAGE_BYTES (2 * 128 * 80 + 2 * 256 * 80)   // 61440
#define SMEM_BYTES (NSTAGE * STAGE_BYTES)           // 184320

// Device scratch (static; no allocations allowed)
__device__ uint32_t g_WkHi[HH * (HH / 2)];                 // bf16x2 [n][h/2]
__device__ uint32_t g_WkLo[HH * (HH / 2)];
__device__ uint32_t g_EHi[(size_t)BB * SS * (HH / 2)];     // bf16x2 [row][h/2]
__device__ uint32_t g_ELo[(size_t)BB * SS * (HH / 2)];
__device__ float    g_q[BB * HH];
__device__ float    g_partial[BB * SS * NTILES];

// ---------------------------------------------------------------------------
// Helpers
// ---------------------------------------------------------------------------
__device__ __forceinline__ uint32_t pack_bf2(__nv_bfloat16 a, __nv_bfloat16 b) {
    __nv_bfloat162 t = __halves2bfloat162(a, b);
    return *reinterpret_cast<uint32_t*>(&t);
}
__device__ __forceinline__ void split_f32(float f, __nv_bfloat16& h, __nv_bfloat16& l) {
    h = __float2bfloat16_rn(f);
    l = __float2bfloat16_rn(f - __bfloat162float(h));
}
__device__ __forceinline__ uint32_t smem_u32(const void* p) {
    uint32_t a;
    asm("{ .reg .u64 t; cvta.to.shared.u64 t, %1; cvt.u32.u64 %0, t; }" : "=r"(a) : "l"(p));
    return a;
}
__device__ __forceinline__ void cp16(uint32_t dst, const void* src) {
    asm volatile("cp.async.cg.shared.global [%0], [%1], 16;\n" :: "r"(dst), "l"(src));
}
#define CP_COMMIT() asm volatile("cp.async.commit_group;\n" ::: "memory")
#define CP_WAIT(n)  asm volatile("cp.async.wait_group %0;\n" :: "n"(n) : "memory")

__device__ __forceinline__ void mma16816(float* d, const uint32_t* a, const uint32_t* b) {
    asm volatile(
        "mma.sync.aligned.m16n8k16.row.col.f32.bf16.bf16.f32 "
        "{%0,%1,%2,%3}, {%4,%5,%6,%7}, {%8,%9}, {%0,%1,%2,%3};\n"
        : "+f"(d[0]), "+f"(d[1]), "+f"(d[2]), "+f"(d[3])
        : "r"(a[0]), "r"(a[1]), "r"(a[2]), "r"(a[3]), "r"(b[0]), "r"(b[1]));
}

// ---------------------------------------------------------------------------
// Prep: split Wk into bf16 hi/lo (K-major rows of 1024)
// ---------------------------------------------------------------------------
__global__ void k_split_wk(const float* __restrict__ Wk) {
    int i8 = blockIdx.x * blockDim.x + threadIdx.x;   // unit of 8 floats
    if (i8 >= HH * HH / 8) return;
    const float4 f0 = *reinterpret_cast<const float4*>(Wk + (size_t)i8 * 8);
    const float4 f1 = *reinterpret_cast<const float4*>(Wk + (size_t)i8 * 8 + 4);
    __nv_bfloat16 h[8], l[8];
    split_f32(f0.x, h[0], l[0]); split_f32(f0.y, h[1], l[1]);
    split_f32(f0.z, h[2], l[2]); split_f32(f0.w, h[3], l[3]);
    split_f32(f1.x, h[4], l[4]); split_f32(f1.y, h[5], l[5]);
    split_f32(f1.z, h[6], l[6]); split_f32(f1.w, h[7], l[7]);
    uint4 hi = { pack_bf2(h[0], h[1]), pack_bf2(h[2], h[3]), pack_bf2(h[4], h[5]), pack_bf2(h[6], h[7]) };
    uint4 lo = { pack_bf2(l[0], l[1]), pack_bf2(l[2], l[3]), pack_bf2(l[4], l[5]), pack_bf2(l[6], l[7]) };
    reinterpret_cast<uint4*>(g_WkHi)[i8] = hi;
    reinterpret_cast<uint4*>(g_WkLo)[i8] = lo;
}

// ---------------------------------------------------------------------------
// Prep: split encoder_outputs into bf16 hi/lo
// ---------------------------------------------------------------------------
__global__ void k_split_enc(const float* __restrict__ enc) {
    size_t i8 = (size_t)blockIdx.x * blockDim.x + threadIdx.x;   // unit of 8 floats
    if (i8 >= (size_t)BB * SS * HH / 8) return;
    const float4 f0 = *reinterpret_cast<const float4*>(enc + i8 * 8);
    const float4 f1 = *reinterpret_cast<const float4*>(enc + i8 * 8 + 4);
    __nv_bfloat16 h[8], l[8];
    split_f32(f0.x, h[0], l[0]); split_f32(f0.y, h[1], l[1]);
    split_f32(f0.z, h[2], l[2]); split_f32(f0.w, h[3], l[3]);
    split_f32(f1.x, h[4], l[4]); split_f32(f1.y, h[5], l[5]);
    split_f32(f1.z, h[6], l[6]); split_f32(f1.w, h[7], l[7]);
    uint4 hi = { pack_bf2(h[0], h[1]), pack_bf2(h[2], h[3]), pack_bf2(h[4], h[5]), pack_bf2(h[6], h[7]) };
    uint4 lo = { pack_bf2(l[0], l[1]), pack_bf2(l[2], l[3]), pack_bf2(l[4], l[5]), pack_bf2(l[6], l[7]) };
    reinterpret_cast<uint4*>(g_EHi)[i8] = hi;
    reinterpret_cast<uint4*>(g_ELo)[i8] = lo;
}

// ---------------------------------------------------------------------------
// Prep: q[b][n] = hidden[b] . Wq[n]
// ---------------------------------------------------------------------------
__global__ void k_query(const float* __restrict__ hidden, const float* __restrict__ Wq) {
    int idx = blockIdx.x * blockDim.x + threadIdx.x;
    if (idx >= BB * HH) return;
    int b = idx >> 10;
    int n = idx & 1023;
    const float* hp = hidden + (size_t)b * HH;
    const float* wp = Wq + (size_t)n * HH;
    float a0 = 0.f, a1 = 0.f, a2 = 0.f, a3 = 0.f;
    #pragma unroll 4
    for (int h = 0; h < HH; h += 4) {
        a0 = fmaf(hp[h + 0], wp[h + 0], a0);
        a1 = fmaf(hp[h + 1], wp[h + 1], a1);
        a2 = fmaf(hp[h + 2], wp[h + 2], a2);
        a3 = fmaf(hp[h + 3], wp[h + 3], a3);
    }
    g_q[idx] = (a0 + a1) + (a2 + a3);
}

// ---------------------------------------------------------------------------
// Main fused kernel: bf16x3 mma.sync GEMM + tanh(q+keys)*v row reduction.
// cp.async 3-stage pipeline on pre-split bf16 operands.
// Grid (NTILES, STILES, BB), ntile fastest for L2 reuse of E tiles.
// ---------------------------------------------------------------------------
__global__ __launch_bounds__(THREADS, 1)
void k_attn(const float* __restrict__ v) {
    extern __shared__ uint32_t smem[];
    __shared__ float s_q[BN];
    __shared__ float s_v[BN];
    __shared__ float s_red[4 * BM];

    const uint32_t sb = smem_u32(smem);

    const int tid = threadIdx.x;
    const int ntile = blockIdx.x;
    const int stile = blockIdx.y;
    const int b = blockIdx.z;
    const int n0 = ntile * BN;
    const size_t eRow0 = (size_t)b * SS + (size_t)stile * BM;

    if (tid < BN) {
        s_q[tid] = g_q[b * HH + n0 + tid];
        s_v[tid] = v[n0 + tid];
    }

    const int lane = tid & 31;
    const int wid  = tid >> 5;
    const int g    = lane >> 2;
    const int tig  = lane & 3;
    const int wm   = wid & 3;        // 4 warps along M (rows of 32)
    const int wn   = wid >> 2;       // 4 warps along N (cols of 64)

    // cp.async: copy chunk c (16 u32 along H) into stage c%NSTAGE
    const int crow = tid >> 2;       // 0..127
    const int ccb  = tid & 3;        // 16B block within 64B row chunk
    auto issue_loads = [&](int c) {
        const uint32_t stg = sb + (uint32_t)(c % NSTAGE) * STAGE_BYTES;
        const int ku = c * 16;
        // A: 128 rows, 4 x 16B per row, hi+lo  (1 iter each)
        {
            uint32_t doff = (uint32_t)(crow * 80 + ccb * 16);
            size_t gsrc = (eRow0 + crow) * (HH / 2) + ku + ccb * 4;
            cp16(stg + OFF_AH + doff, g_EHi + gsrc);
            cp16(stg + OFF_AL + doff, g_ELo + gsrc);
        }
        // B: 256 rows, 4 x 16B per row, hi+lo  (2 iters each)
        #pragma unroll
        for (int i = 0; i < 2; ++i) {
            int row = crow + i * 128;
            uint32_t doff = (uint32_t)(row * 80 + ccb * 16);
            size_t gsrc = (size_t)(n0 + row) * (HH / 2) + ku + ccb * 4;
            cp16(stg + OFF_BH + doff, g_WkHi + gsrc);
            cp16(stg + OFF_BL + doff, g_WkLo + gsrc);
        }
    };

    float C[2][8][4];
    #pragma unroll
    for (int mt = 0; mt < 2; ++mt)
        #pragma unroll
        for (int nt = 0; nt < 8; ++nt)
            #pragma unroll
            for (int r = 0; r < 4; ++r) C[mt][nt][r] = 0.f;

    issue_loads(0); CP_COMMIT();
    issue_loads(1); CP_COMMIT();
    issue_loads(2); CP_COMMIT();

    for (int c = 0; c < NCHUNK; ++c) {
        CP_WAIT(2);              // group c complete
        __syncthreads();

        const uint32_t* stg = smem + (size_t)(c % NSTAGE) * (STAGE_BYTES / 4);
        const uint32_t* ah = stg + OFF_AH / 4;
        const uint32_t* al = stg + OFF_AL / 4;
        const uint32_t* bh = stg + OFF_BH / 4;
        const uint32_t* bl = stg + OFF_BL / 4;

        #pragma unroll
        for (int ks = 0; ks < 2; ++ks) {
            const int kp = ks * 8 + tig;
            uint32_t Ah[2][4], Al[2][4];
            #pragma unroll
            for (int mt = 0; mt < 2; ++mt) {
                int r0 = wm * 32 + mt * 16 + g;
                Ah[mt][0] = ah[r0 * ROW_U32 + kp];
                Ah[mt][1] = ah[(r0 + 8) * ROW_U32 + kp];
                Ah[mt][2] = ah[r0 * ROW_U32 + kp + 4];
                Ah[mt][3] = ah[(r0 + 8) * ROW_U32 + kp + 4];
                Al[mt][0] = al[r0 * ROW_U32 + kp];
                Al[mt][1] = al[(r0 + 8) * ROW_U32 + kp];
                Al[mt][2] = al[r0 * ROW_U32 + kp + 4];
                Al[mt][3] = al[(r0 + 8) * ROW_U32 + kp + 4];
            }
            #pragma unroll
            for (int nt = 0; nt < 8; ++nt) {
                int br = wn * 64 + nt * 8 + g;
                uint32_t Bh[2] = { bh[br * ROW_U32 + kp], bh[br * ROW_U32 + kp + 4] };
                uint32_t Bl[2] = { bl[br * ROW_U32 + kp], bl[br * ROW_U32 + kp + 4] };
                #pragma unroll
                for (int mt = 0; mt < 2; ++mt) {
                    mma16816(C[mt][nt], Ah[mt], Bh);   // hi*hi
                    mma16816(C[mt][nt], Al[mt], Bh);   // lo*hi
                    mma16816(C[mt][nt], Ah[mt], Bl);   // hi*lo
                }
            }
        }

        if (c + NSTAGE < NCHUNK) {
            __syncthreads();     // all warps done with stage (c%NSTAGE) before refill
            issue_loads(c + NSTAGE); CP_COMMIT();
        }
    }

    // ---- epilogue: tanh(q + keys) * v, reduce over this CTA's BN columns ----
    float rs[2][2] = {{0.f, 0.f}, {0.f, 0.f}};
    #pragma unroll
    for (int mt = 0; mt < 2; ++mt)
        #pragma unroll
        for (int nt = 0; nt < 8; ++nt)
            #pragma unroll
            for (int r = 0; r < 4; ++r) {
                int col = wn * 64 + nt * 8 + tig * 2 + (r & 1);
                float e = tanhf(s_q[col] + C[mt][nt][r]) * s_v[col];
                rs[mt][r >> 1] += e;
            }

    #pragma unroll
    for (int mt = 0; mt < 2; ++mt)
        #pragma unroll
        for (int hh = 0; hh < 2; ++hh) {
            float x = rs[mt][hh];
            x += __shfl_xor_sync(0xffffffffu, x, 1);
            x += __shfl_xor_sync(0xffffffffu, x, 2);
            if (tig == 0) {
                int row = wm * 32 + mt * 16 + hh * 8 + g;
                s_red[wn * BM + row] = x;
            }
        }
    __syncthreads();

    if (tid < BM) {
        float t = s_red[tid] + s_red[BM + tid] + s_red[2 * BM + tid] + s_red[3 * BM + tid];
        g_partial[(eRow0 + tid) * NTILES + ntile] = t;
    }
}

// ---------------------------------------------------------------------------
// Masked softmax over S per batch. lengths is int32 (JAX downcast).
// ---------------------------------------------------------------------------
__global__ void k_softmax(const int* __restrict__ lengths, float* __restrict__ out) {
    const int b = blockIdx.x;
    const int tid = threadIdx.x;      // 256 threads
    const int lane = tid & 31, wid = tid >> 5;
    int len = lengths[b];
    if (len < 1) len = 1;

    float a[8];
    float mx = -INFINITY;
    #pragma unroll
    for (int i = 0; i < 8; ++i) {
        int s = tid + i * 256;
        const float* p = &g_partial[((size_t)b * SS + s) * NTILES];
        float vv = (p[0] + p[1]) + (p[2] + p[3]);
        if (s >= len) vv = -INFINITY;
        a[i] = vv;
        mx = fmaxf(mx, vv);
    }

    __shared__ float smax[8];
    __shared__ float ssum[8];

    #pragma unroll
    for (int o = 16; o > 0; o >>= 1) mx = fmaxf(mx, __shfl_xor_sync(0xffffffffu, mx, o));
    if (lane == 0) smax[wid] = mx;
    __syncthreads();
    if (wid == 0) {
        float t = (lane < 8) ? smax[lane] : -INFINITY;
        #pragma unroll
        for (int o = 4; o > 0; o >>= 1) t = fmaxf(t, __shfl_xor_sync(0xffffffffu, t, o));
        if (lane == 0) smax[0] = t;
    }
    __syncthreads();
    mx = smax[0];

    float sum = 0.f;
    #pragma unroll
    for (int i = 0; i < 8; ++i) {
        float e = expf(a[i] - mx);
        a[i] = e;
        sum += e;
    }
    #pragma unroll
    for (int o = 16; o > 0; o >>= 1) sum += __shfl_xor_sync(0xffffffffu, sum, o);
    if (lane == 0) ssum[wid] = sum;
    __syncthreads();
    if (wid == 0) {
        float t = (lane < 8) ? ssum[lane] : 0.f;
        #pragma unroll
        for (int o = 4; o > 0; o >>= 1) t += __shfl_xor_sync(0xffffffffu, t, o);
        if (lane == 0) ssum[0] = t;
    }
    __syncthreads();
    const float inv = 1.f / ssum[0];

    #pragma unroll
    for (int i = 0; i < 8; ++i) {
        int s = tid + i * 256;
        out[(size_t)b * SS + s] = a[i] * inv;
    }
}

// ---------------------------------------------------------------------------
extern "C" void kernel_launch(void* const* d_in, const int* in_sizes, int n_in,
                              void* d_out, int out_size) {
    const float* hidden  = (const float*)d_in[0];
    const float* enc     = (const float*)d_in[1];
    const int*   lengths = (const int*)d_in[2];    // int32 (JAX downcast)
    const float* Wq      = (const float*)d_in[3];
    const float* Wk      = (const float*)d_in[4];
    const float* v       = (const float*)d_in[5];
    float* out = (float*)d_out;

    cudaFuncSetAttribute(k_attn, cudaFuncAttributeMaxDynamicSharedMemorySize, SMEM_BYTES);

    k_split_wk<<<(HH * HH / 8 + 255) / 256, 256>>>(Wk);
    k_split_enc<<<(int)(((size_t)BB * SS * HH / 8 + 255) / 256), 256>>>(enc);
    k_query<<<(BB * HH + 255) / 256, 256>>>(hidden, Wq);

    dim3 grid(NTILES, STILES, BB);
    k_attn<<<grid, THREADS, SMEM_BYTES>>>(v);

    k_softmax<<<BB, 256>>>(lengths, out);
}

// round 10
// speedup vs baseline: 1.1701x; 1.0821x over previous
#include <cuda_runtime.h>
#include <cuda_bf16.h>
#include <cstdint>
#include <math.h>

// Problem constants
#define BB 32
#define SS 2048
#define HH 1024

// Tiling
#define BM 128
#define BN 256
#define KC 32                   // K elements per chunk (16 u32 of bf16x2)
#define NTILES (HH / BN)        // 4
#define STILES (SS / BM)        // 16
#define NCHUNK (HH / KC)        // 32
#define THREADS 512
#define NSTAGE 3

// Per-stage smem layout (bytes). Rows padded 64B->80B (20 u32): 16B-aligned
// for cp.async, conflict-free for ldmatrix (8 rows @ stride 20 u32 cover all banks).
#define ROW_U32 20
#define OFF_AH 0
#define OFF_AL (128 * 80)                 // 10240
#define OFF_BH (2 * 128 * 80)             // 20480
#define OFF_BL (2 * 128 * 80 + 256 * 80)  // 40960
#define STAGE_BYTES (2 * 128 * 80 + 2 * 256 * 80)   // 61440
#define SMEM_BYTES (NSTAGE * STAGE_BYTES)           // 184320

// Device scratch (static; no allocations allowed)
__device__ uint32_t g_WkHi[HH * (HH / 2)];                 // bf16x2 [n][h/2]
__device__ uint32_t g_WkLo[HH * (HH / 2)];
__device__ uint32_t g_EHi[(size_t)BB * SS * (HH / 2)];     // bf16x2 [row][h/2]
__device__ uint32_t g_ELo[(size_t)BB * SS * (HH / 2)];
__device__ float    g_q[BB * HH];
__device__ float    g_partial[BB * SS * NTILES];

// ---------------------------------------------------------------------------
// Helpers
// ---------------------------------------------------------------------------
__device__ __forceinline__ uint32_t pack_bf2(__nv_bfloat16 a, __nv_bfloat16 b) {
    __nv_bfloat162 t = __halves2bfloat162(a, b);
    return *reinterpret_cast<uint32_t*>(&t);
}
__device__ __forceinline__ void split_f32(float f, __nv_bfloat16& h, __nv_bfloat16& l) {
    h = __float2bfloat16_rn(f);
    l = __float2bfloat16_rn(f - __bfloat162float(h));
}
__device__ __forceinline__ uint32_t smem_u32(const void* p) {
    uint32_t a;
    asm("{ .reg .u64 t; cvta.to.shared.u64 t, %1; cvt.u32.u64 %0, t; }" : "=r"(a) : "l"(p));
    return a;
}
__device__ __forceinline__ void cp16(uint32_t dst, const void* src) {
    asm volatile("cp.async.cg.shared.global [%0], [%1], 16;\n" :: "r"(dst), "l"(src));
}
#define CP_COMMIT() asm volatile("cp.async.commit_group;\n" ::: "memory")
#define CP_WAIT(n)  asm volatile("cp.async.wait_group %0;\n" :: "n"(n) : "memory")

#define LDSM4(r0, r1, r2, r3, addr) \
    asm volatile("ldmatrix.sync.aligned.m8n8.x4.shared.b16 {%0,%1,%2,%3}, [%4];" \
        : "=r"(r0), "=r"(r1), "=r"(r2), "=r"(r3) : "r"(addr))

__device__ __forceinline__ void mma16816(float* d, const uint32_t* a, const uint32_t* b) {
    asm volatile(
        "mma.sync.aligned.m16n8k16.row.col.f32.bf16.bf16.f32 "
        "{%0,%1,%2,%3}, {%4,%5,%6,%7}, {%8,%9}, {%0,%1,%2,%3};\n"
        : "+f"(d[0]), "+f"(d[1]), "+f"(d[2]), "+f"(d[3])
        : "r"(a[0]), "r"(a[1]), "r"(a[2]), "r"(a[3]), "r"(b[0]), "r"(b[1]));
}

// ---------------------------------------------------------------------------
// Prep: split Wk into bf16 hi/lo (K-major rows of 1024)
// ---------------------------------------------------------------------------
__global__ void k_split_wk(const float* __restrict__ Wk) {
    int i8 = blockIdx.x * blockDim.x + threadIdx.x;   // unit of 8 floats
    if (i8 >= HH * HH / 8) return;
    const float4 f0 = *reinterpret_cast<const float4*>(Wk + (size_t)i8 * 8);
    const float4 f1 = *reinterpret_cast<const float4*>(Wk + (size_t)i8 * 8 + 4);
    __nv_bfloat16 h[8], l[8];
    split_f32(f0.x, h[0], l[0]); split_f32(f0.y, h[1], l[1]);
    split_f32(f0.z, h[2], l[2]); split_f32(f0.w, h[3], l[3]);
    split_f32(f1.x, h[4], l[4]); split_f32(f1.y, h[5], l[5]);
    split_f32(f1.z, h[6], l[6]); split_f32(f1.w, h[7], l[7]);
    uint4 hi = { pack_bf2(h[0], h[1]), pack_bf2(h[2], h[3]), pack_bf2(h[4], h[5]), pack_bf2(h[6], h[7]) };
    uint4 lo = { pack_bf2(l[0], l[1]), pack_bf2(l[2], l[3]), pack_bf2(l[4], l[5]), pack_bf2(l[6], l[7]) };
    reinterpret_cast<uint4*>(g_WkHi)[i8] = hi;
    reinterpret_cast<uint4*>(g_WkLo)[i8] = lo;
}

// ---------------------------------------------------------------------------
// Prep: split encoder_outputs into bf16 hi/lo
// ---------------------------------------------------------------------------
__global__ void k_split_enc(const float* __restrict__ enc) {
    size_t i8 = (size_t)blockIdx.x * blockDim.x + threadIdx.x;   // unit of 8 floats
    if (i8 >= (size_t)BB * SS * HH / 8) return;
    const float4 f0 = *reinterpret_cast<const float4*>(enc + i8 * 8);
    const float4 f1 = *reinterpret_cast<const float4*>(enc + i8 * 8 + 4);
    __nv_bfloat16 h[8], l[8];
    split_f32(f0.x, h[0], l[0]); split_f32(f0.y, h[1], l[1]);
    split_f32(f0.z, h[2], l[2]); split_f32(f0.w, h[3], l[3]);
    split_f32(f1.x, h[4], l[4]); split_f32(f1.y, h[5], l[5]);
    split_f32(f1.z, h[6], l[6]); split_f32(f1.w, h[7], l[7]);
    uint4 hi = { pack_bf2(h[0], h[1]), pack_bf2(h[2], h[3]), pack_bf2(h[4], h[5]), pack_bf2(h[6], h[7]) };
    uint4 lo = { pack_bf2(l[0], l[1]), pack_bf2(l[2], l[3]), pack_bf2(l[4], l[5]), pack_bf2(l[6], l[7]) };
    reinterpret_cast<uint4*>(g_EHi)[i8] = hi;
    reinterpret_cast<uint4*>(g_ELo)[i8] = lo;
}

// ---------------------------------------------------------------------------
// Prep: q[b][n] = hidden[b] . Wq[n]
// ---------------------------------------------------------------------------
__global__ void k_query(const float* __restrict__ hidden, const float* __restrict__ Wq) {
    int idx = blockIdx.x * blockDim.x + threadIdx.x;
    if (idx >= BB * HH) return;
    int b = idx >> 10;
    int n = idx & 1023;
    const float* hp = hidden + (size_t)b * HH;
    const float* wp = Wq + (size_t)n * HH;
    float a0 = 0.f, a1 = 0.f, a2 = 0.f, a3 = 0.f;
    #pragma unroll 4
    for (int h = 0; h < HH; h += 4) {
        a0 = fmaf(hp[h + 0], wp[h + 0], a0);
        a1 = fmaf(hp[h + 1], wp[h + 1], a1);
        a2 = fmaf(hp[h + 2], wp[h + 2], a2);
        a3 = fmaf(hp[h + 3], wp[h + 3], a3);
    }
    g_q[idx] = (a0 + a1) + (a2 + a3);
}

// ---------------------------------------------------------------------------
// Main fused kernel: bf16x3 mma.sync GEMM + tanh(q+keys)*v row reduction.
// ldmatrix fragment loads, single __syncthreads per chunk, 3-stage cp.async.
// Grid (NTILES, STILES, BB), ntile fastest for L2 reuse of E tiles.
// ---------------------------------------------------------------------------
__global__ __launch_bounds__(THREADS, 1)
void k_attn(const float* __restrict__ v) {
    extern __shared__ uint32_t smem[];
    __shared__ float s_q[BN];
    __shared__ float s_v[BN];
    __shared__ float s_red[4 * BM];

    const uint32_t sb = smem_u32(smem);

    const int tid = threadIdx.x;
    const int ntile = blockIdx.x;
    const int stile = blockIdx.y;
    const int b = blockIdx.z;
    const int n0 = ntile * BN;
    const size_t eRow0 = (size_t)b * SS + (size_t)stile * BM;

    if (tid < BN) {
        s_q[tid] = g_q[b * HH + n0 + tid];
        s_v[tid] = v[n0 + tid];
    }

    const int lane = tid & 31;
    const int wid  = tid >> 5;
    const int g    = lane >> 2;
    const int tig  = lane & 3;
    const int wm   = wid & 3;        // 4 warps along M (rows of 32)
    const int wn   = wid >> 2;       // 4 warps along N (cols of 64)

    // ldmatrix per-lane byte offsets within stage
    const int l7 = lane & 7;
    // A x4: lanes 0-7 rows m0-7 k0 | 8-15 rows m8-15 k0 | 16-23 m0-7 k8(+16B) | 24-31 m8-15 k8
    const uint32_t aOff = (uint32_t)((wm * 32 + l7 + ((lane >> 3) & 1) * 8) * 80
                                     + ((lane >> 4) & 1) * 16);
    // B x4 (pair of nt): 0-7 n0-7 k0 | 8-15 n0-7 k8 | 16-23 n8-15 k0 | 24-31 n8-15 k8
    const uint32_t bOff = (uint32_t)((wn * 64 + l7 + (lane >> 4) * 8) * 80
                                     + ((lane >> 3) & 1) * 16);

    // cp.async: copy chunk c (16 u32 along H) into stage c%NSTAGE
    const int crow = tid >> 2;       // 0..127
    const int ccb  = tid & 3;        // 16B block within 64B row chunk
    auto issue_loads = [&](int c) {
        const uint32_t stg = sb + (uint32_t)(c % NSTAGE) * STAGE_BYTES;
        const int ku = c * 16;
        {
            uint32_t doff = (uint32_t)(crow * 80 + ccb * 16);
            size_t gsrc = (eRow0 + crow) * (HH / 2) + ku + ccb * 4;
            cp16(stg + OFF_AH + doff, g_EHi + gsrc);
            cp16(stg + OFF_AL + doff, g_ELo + gsrc);
        }
        #pragma unroll
        for (int i = 0; i < 2; ++i) {
            int row = crow + i * 128;
            uint32_t doff = (uint32_t)(row * 80 + ccb * 16);
            size_t gsrc = (size_t)(n0 + row) * (HH / 2) + ku + ccb * 4;
            cp16(stg + OFF_BH + doff, g_WkHi + gsrc);
            cp16(stg + OFF_BL + doff, g_WkLo + gsrc);
        }
    };

    float C[2][8][4];
    #pragma unroll
    for (int mt = 0; mt < 2; ++mt)
        #pragma unroll
        for (int nt = 0; nt < 8; ++nt)
            #pragma unroll
            for (int r = 0; r < 4; ++r) C[mt][nt][r] = 0.f;

    issue_loads(0); CP_COMMIT();
    issue_loads(1); CP_COMMIT();

    for (int c = 0; c < NCHUNK; ++c) {
        CP_WAIT(1);              // group for chunk c complete (see tail note)
        __syncthreads();

        // refill stage (c+2)%NSTAGE — drained: last read in iter c-1.
        // Always commit (possibly empty group) so CP_WAIT(1) stays correct at tail.
        if (c + 2 < NCHUNK) issue_loads(c + 2);
        CP_COMMIT();

        const uint32_t stgA = sb + (uint32_t)(c % NSTAGE) * STAGE_BYTES + aOff;
        const uint32_t stgB = sb + (uint32_t)(c % NSTAGE) * STAGE_BYTES + OFF_BH + bOff;

        #pragma unroll
        for (int ks = 0; ks < 2; ++ks) {
            uint32_t Ah[2][4], Al[2][4];
            #pragma unroll
            for (int mt = 0; mt < 2; ++mt) {
                LDSM4(Ah[mt][0], Ah[mt][1], Ah[mt][2], Ah[mt][3],
                      stgA + (uint32_t)(ks * 32 + mt * 1280));
                LDSM4(Al[mt][0], Al[mt][1], Al[mt][2], Al[mt][3],
                      stgA + (uint32_t)(OFF_AL + ks * 32 + mt * 1280));
            }
            #pragma unroll
            for (int pair = 0; pair < 4; ++pair) {
                uint32_t Bh[4], Bl[4];
                LDSM4(Bh[0], Bh[1], Bh[2], Bh[3],
                      stgB + (uint32_t)(ks * 32 + pair * 1280));
                LDSM4(Bl[0], Bl[1], Bl[2], Bl[3],
                      stgB + (uint32_t)((OFF_BL - OFF_BH) + ks * 32 + pair * 1280));
                #pragma unroll
                for (int sub = 0; sub < 2; ++sub) {
                    const int nt = pair * 2 + sub;
                    uint32_t bh2[2] = { Bh[2 * sub], Bh[2 * sub + 1] };
                    uint32_t bl2[2] = { Bl[2 * sub], Bl[2 * sub + 1] };
                    #pragma unroll
                    for (int mt = 0; mt < 2; ++mt) {
                        mma16816(C[mt][nt], Ah[mt], bh2);   // hi*hi
                        mma16816(C[mt][nt], Al[mt], bh2);   // lo*hi
                        mma16816(C[mt][nt], Ah[mt], bl2);   // hi*lo
                    }
                }
            }
        }
    }

    // ---- epilogue: tanh(q + keys) * v, reduce over this CTA's BN columns ----
    float rs[2][2] = {{0.f, 0.f}, {0.f, 0.f}};
    #pragma unroll
    for (int mt = 0; mt < 2; ++mt)
        #pragma unroll
        for (int nt = 0; nt < 8; ++nt)
            #pragma unroll
            for (int r = 0; r < 4; ++r) {
                int col = wn * 64 + nt * 8 + tig * 2 + (r & 1);
                float e = tanhf(s_q[col] + C[mt][nt][r]) * s_v[col];
                rs[mt][r >> 1] += e;
            }

    #pragma unroll
    for (int mt = 0; mt < 2; ++mt)
        #pragma unroll
        for (int hh = 0; hh < 2; ++hh) {
            float x = rs[mt][hh];
            x += __shfl_xor_sync(0xffffffffu, x, 1);
            x += __shfl_xor_sync(0xffffffffu, x, 2);
            if (tig == 0) {
                int row = wm * 32 + mt * 16 + hh * 8 + g;
                s_red[wn * BM + row] = x;
            }
        }
    __syncthreads();

    if (tid < BM) {
        float t = s_red[tid] + s_red[BM + tid] + s_red[2 * BM + tid] + s_red[3 * BM + tid];
        g_partial[(eRow0 + tid) * NTILES + ntile] = t;
    }
}

// ---------------------------------------------------------------------------
// Masked softmax over S per batch. lengths is int32 (JAX downcast).
// ---------------------------------------------------------------------------
__global__ void k_softmax(const int* __restrict__ lengths, float* __restrict__ out) {
    const int b = blockIdx.x;
    const int tid = threadIdx.x;      // 256 threads
    const int lane = tid & 31, wid = tid >> 5;
    int len = lengths[b];
    if (len < 1) len = 1;

    float a[8];
    float mx = -INFINITY;
    #pragma unroll
    for (int i = 0; i < 8; ++i) {
        int s = tid + i * 256;
        const float* p = &g_partial[((size_t)b * SS + s) * NTILES];
        float vv = (p[0] + p[1]) + (p[2] + p[3]);
        if (s >= len) vv = -INFINITY;
        a[i] = vv;
        mx = fmaxf(mx, vv);
    }

    __shared__ float smax[8];
    __shared__ float ssum[8];

    #pragma unroll
    for (int o = 16; o > 0; o >>= 1) mx = fmaxf(mx, __shfl_xor_sync(0xffffffffu, mx, o));
    if (lane == 0) smax[wid] = mx;
    __syncthreads();
    if (wid == 0) {
        float t = (lane < 8) ? smax[lane] : -INFINITY;
        #pragma unroll
        for (int o = 4; o > 0; o >>= 1) t = fmaxf(t, __shfl_xor_sync(0xffffffffu, t, o));
        if (lane == 0) smax[0] = t;
    }
    __syncthreads();
    mx = smax[0];

    float sum = 0.f;
    #pragma unroll
    for (int i = 0; i < 8; ++i) {
        float e = expf(a[i] - mx);
        a[i] = e;
        sum += e;
    }
    #pragma unroll
    for (int o = 16; o > 0; o >>= 1) sum += __shfl_xor_sync(0xffffffffu, sum, o);
    if (lane == 0) ssum[wid] = sum;
    __syncthreads();
    if (wid == 0) {
        float t = (lane < 8) ? ssum[lane] : 0.f;
        #pragma unroll
        for (int o = 4; o > 0; o >>= 1) t += __shfl_xor_sync(0xffffffffu, t, o);
        if (lane == 0) ssum[0] = t;
    }
    __syncthreads();
    const float inv = 1.f / ssum[0];

    #pragma unroll
    for (int i = 0; i < 8; ++i) {
        int s = tid + i * 256;
        out[(size_t)b * SS + s] = a[i] * inv;
    }
}

// ---------------------------------------------------------------------------
extern "C" void kernel_launch(void* const* d_in, const int* in_sizes, int n_in,
                              void* d_out, int out_size) {
    const float* hidden  = (const float*)d_in[0];
    const float* enc     = (const float*)d_in[1];
    const int*   lengths = (const int*)d_in[2];    // int32 (JAX downcast)
    const float* Wq      = (const float*)d_in[3];
    const float* Wk      = (const float*)d_in[4];
    const float* v       = (const float*)d_in[5];
    float* out = (float*)d_out;

    cudaFuncSetAttribute(k_attn, cudaFuncAttributeMaxDynamicSharedMemorySize, SMEM_BYTES);

    k_split_wk<<<(HH * HH / 8 + 255) / 256, 256>>>(Wk);
    k_split_enc<<<(int)(((size_t)BB * SS * HH / 8 + 255) / 256), 256>>>(enc);
    k_query<<<(BB * HH + 255) / 256, 256>>>(hidden, Wq);

    dim3 grid(NTILES, STILES, BB);
    k_attn<<<grid, THREADS, SMEM_BYTES>>>(v);

    k_softmax<<<BB, 256>>>(lengths, out);
}

// round 12
// speedup vs baseline: 1.3584x; 1.1609x over previous
#include <cuda_runtime.h>
#include <cuda_bf16.h>
#include <cstdint>
#include <math.h>

// Problem constants
#define BB 32
#define SS 2048
#define HH 1024

// Tiling
#define BM 128
#define BN 256
#define KC 32                   // K elements per chunk (16 u32 of bf16x2)
#define NTILES (HH / BN)        // 4
#define STILES (SS / BM)        // 16
#define NCHUNK (HH / KC)        // 32
#define THREADS 512
#define NSTAGE 3

// Per-stage smem layout (bytes). Rows padded 64B->80B (20 u32): 16B-aligned
// for cp.async, conflict-free for ldmatrix (8 rows @ stride 20 u32 cover all banks).
#define ROW_U32 20
#define OFF_AH 0
#define OFF_AL (128 * 80)                 // 10240
#define OFF_BH (2 * 128 * 80)             // 20480
#define OFF_BL (2 * 128 * 80 + 256 * 80)  // 40960
#define STAGE_BYTES (2 * 128 * 80 + 2 * 256 * 80)   // 61440
#define SMEM_BYTES (NSTAGE * STAGE_BYTES)           // 184320

// Device scratch (static; no allocations allowed)
__device__ uint32_t g_WkHi[HH * (HH / 2)];                 // bf16x2 [n][h/2]
__device__ uint32_t g_WkLo[HH * (HH / 2)];
__device__ uint32_t g_EHi[(size_t)BB * SS * (HH / 2)];     // bf16x2 [row][h/2]
__device__ uint32_t g_ELo[(size_t)BB * SS * (HH / 2)];
__device__ float    g_q[BB * HH];
__device__ float    g_partial[BB * SS * NTILES];

// ---------------------------------------------------------------------------
// Helpers
// ---------------------------------------------------------------------------
__device__ __forceinline__ uint32_t pack_bf2(__nv_bfloat16 a, __nv_bfloat16 b) {
    __nv_bfloat162 t = __halves2bfloat162(a, b);
    return *reinterpret_cast<uint32_t*>(&t);
}
__device__ __forceinline__ void split_f32(float f, __nv_bfloat16& h, __nv_bfloat16& l) {
    h = __float2bfloat16_rn(f);
    l = __float2bfloat16_rn(f - __bfloat162float(h));
}
__device__ __forceinline__ uint32_t smem_u32(const void* p) {
    uint32_t a;
    asm("{ .reg .u64 t; cvta.to.shared.u64 t, %1; cvt.u32.u64 %0, t; }" : "=r"(a) : "l"(p));
    return a;
}
__device__ __forceinline__ void cp16(uint32_t dst, const void* src) {
    asm volatile("cp.async.cg.shared.global [%0], [%1], 16;\n" :: "r"(dst), "l"(src));
}
#define CP_COMMIT() asm volatile("cp.async.commit_group;\n" ::: "memory")
#define CP_WAIT(n)  asm volatile("cp.async.wait_group %0;\n" :: "n"(n) : "memory")

#define LDSM4(r0, r1, r2, r3, addr) \
    asm volatile("ldmatrix.sync.aligned.m8n8.x4.shared.b16 {%0,%1,%2,%3}, [%4];" \
        : "=r"(r0), "=r"(r1), "=r"(r2), "=r"(r3) : "r"(addr))

__device__ __forceinline__ void mma16816(float* d, const uint32_t* a, const uint32_t* b) {
    asm volatile(
        "mma.sync.aligned.m16n8k16.row.col.f32.bf16.bf16.f32 "
        "{%0,%1,%2,%3}, {%4,%5,%6,%7}, {%8,%9}, {%0,%1,%2,%3};\n"
        : "+f"(d[0]), "+f"(d[1]), "+f"(d[2]), "+f"(d[3])
        : "r"(a[0]), "r"(a[1]), "r"(a[2]), "r"(a[3]), "r"(b[0]), "r"(b[1]));
}

// ---------------------------------------------------------------------------
// Prep: split Wk into bf16 hi/lo (K-major rows of 1024)
// ---------------------------------------------------------------------------
__global__ void k_split_wk(const float* __restrict__ Wk) {
    int i8 = blockIdx.x * blockDim.x + threadIdx.x;   // unit of 8 floats
    if (i8 >= HH * HH / 8) return;
    const float4 f0 = *reinterpret_cast<const float4*>(Wk + (size_t)i8 * 8);
    const float4 f1 = *reinterpret_cast<const float4*>(Wk + (size_t)i8 * 8 + 4);
    __nv_bfloat16 h[8], l[8];
    split_f32(f0.x, h[0], l[0]); split_f32(f0.y, h[1], l[1]);
    split_f32(f0.z, h[2], l[2]); split_f32(f0.w, h[3], l[3]);
    split_f32(f1.x, h[4], l[4]); split_f32(f1.y, h[5], l[5]);
    split_f32(f1.z, h[6], l[6]); split_f32(f1.w, h[7], l[7]);
    uint4 hi = { pack_bf2(h[0], h[1]), pack_bf2(h[2], h[3]), pack_bf2(h[4], h[5]), pack_bf2(h[6], h[7]) };
    uint4 lo = { pack_bf2(l[0], l[1]), pack_bf2(l[2], l[3]), pack_bf2(l[4], l[5]), pack_bf2(l[6], l[7]) };
    reinterpret_cast<uint4*>(g_WkHi)[i8] = hi;
    reinterpret_cast<uint4*>(g_WkLo)[i8] = lo;
}

// ---------------------------------------------------------------------------
// Prep: split encoder_outputs into bf16 hi/lo.
// Skips rows s >= ceil(len/BM)*BM — those rows are never read by k_attn
// (whole stile skipped) and the softmax masks them, so both the global read
// and write are dead work.
// ---------------------------------------------------------------------------
__global__ void k_split_enc(const float* __restrict__ enc, const int* __restrict__ lengths) {
    size_t i8 = (size_t)blockIdx.x * blockDim.x + threadIdx.x;   // unit of 8 floats
    if (i8 >= (size_t)BB * SS * HH / 8) return;
    const int row = (int)(i8 / (HH / 8));
    const int b = row / SS;
    const int s = row % SS;
    int len = lengths[b];
    if (len < 1) len = 1;
    const int lim = (len + BM - 1) & ~(BM - 1);   // round up to stile granularity
    if (s >= lim) return;                          // dead row: skip read+write
    const float4 f0 = *reinterpret_cast<const float4*>(enc + i8 * 8);
    const float4 f1 = *reinterpret_cast<const float4*>(enc + i8 * 8 + 4);
    __nv_bfloat16 h[8], l[8];
    split_f32(f0.x, h[0], l[0]); split_f32(f0.y, h[1], l[1]);
    split_f32(f0.z, h[2], l[2]); split_f32(f0.w, h[3], l[3]);
    split_f32(f1.x, h[4], l[4]); split_f32(f1.y, h[5], l[5]);
    split_f32(f1.z, h[6], l[6]); split_f32(f1.w, h[7], l[7]);
    uint4 hi = { pack_bf2(h[0], h[1]), pack_bf2(h[2], h[3]), pack_bf2(h[4], h[5]), pack_bf2(h[6], h[7]) };
    uint4 lo = { pack_bf2(l[0], l[1]), pack_bf2(l[2], l[3]), pack_bf2(l[4], l[5]), pack_bf2(l[6], l[7]) };
    reinterpret_cast<uint4*>(g_EHi)[i8] = hi;
    reinterpret_cast<uint4*>(g_ELo)[i8] = lo;
}

// ---------------------------------------------------------------------------
// Prep: q[b][n] = hidden[b] . Wq[n]
// ---------------------------------------------------------------------------
__global__ void k_query(const float* __restrict__ hidden, const float* __restrict__ Wq) {
    int idx = blockIdx.x * blockDim.x + threadIdx.x;
    if (idx >= BB * HH) return;
    int b = idx >> 10;
    int n = idx & 1023;
    const float* hp = hidden + (size_t)b * HH;
    const float* wp = Wq + (size_t)n * HH;
    float a0 = 0.f, a1 = 0.f, a2 = 0.f, a3 = 0.f;
    #pragma unroll 4
    for (int h = 0; h < HH; h += 4) {
        a0 = fmaf(hp[h + 0], wp[h + 0], a0);
        a1 = fmaf(hp[h + 1], wp[h + 1], a1);
        a2 = fmaf(hp[h + 2], wp[h + 2], a2);
        a3 = fmaf(hp[h + 3], wp[h + 3], a3);
    }
    g_q[idx] = (a0 + a1) + (a2 + a3);
}

// ---------------------------------------------------------------------------
// Main fused kernel: bf16x3 mma.sync GEMM + tanh(q+keys)*v row reduction.
// ldmatrix fragment loads, single __syncthreads per chunk, 3-stage cp.async.
// Length-aware: CTAs whose stile is fully masked exit immediately (their
// g_partial slots are garbage, overwritten by the softmax mask).
// Grid (NTILES, STILES, BB), ntile fastest for L2 reuse of E tiles.
// ---------------------------------------------------------------------------
__global__ __launch_bounds__(THREADS, 1)
void k_attn(const float* __restrict__ v, const int* __restrict__ lengths) {
    extern __shared__ uint32_t smem[];
    __shared__ float s_q[BN];
    __shared__ float s_v[BN];
    __shared__ float s_red[4 * BM];

    const uint32_t sb = smem_u32(smem);

    const int tid = threadIdx.x;
    const int ntile = blockIdx.x;
    const int stile = blockIdx.y;
    const int b = blockIdx.z;

    // Length-aware early exit: every row in this stile is masked.
    // Uniform per-CTA condition, before any barrier -> convergent.
    if (stile * BM >= lengths[b]) return;

    const int n0 = ntile * BN;
    const size_t eRow0 = (size_t)b * SS + (size_t)stile * BM;

    if (tid < BN) {
        s_q[tid] = g_q[b * HH + n0 + tid];
        s_v[tid] = v[n0 + tid];
    }

    const int lane = tid & 31;
    const int wid  = tid >> 5;
    const int g    = lane >> 2;
    const int tig  = lane & 3;
    const int wm   = wid & 3;        // 4 warps along M (rows of 32)
    const int wn   = wid >> 2;       // 4 warps along N (cols of 64)

    // ldmatrix per-lane byte offsets within stage
    const int l7 = lane & 7;
    // A x4: lanes 0-7 rows m0-7 k0 | 8-15 rows m8-15 k0 | 16-23 m0-7 k8(+16B) | 24-31 m8-15 k8
    const uint32_t aOff = (uint32_t)((wm * 32 + l7 + ((lane >> 3) & 1) * 8) * 80
                                     + ((lane >> 4) & 1) * 16);
    // B x4 (pair of nt): 0-7 n0-7 k0 | 8-15 n0-7 k8 | 16-23 n8-15 k0 | 24-31 n8-15 k8
    const uint32_t bOff = (uint32_t)((wn * 64 + l7 + (lane >> 4) * 8) * 80
                                     + ((lane >> 3) & 1) * 16);

    // cp.async: copy chunk c (16 u32 along H) into stage c%NSTAGE
    const int crow = tid >> 2;       // 0..127
    const int ccb  = tid & 3;        // 16B block within 64B row chunk
    auto issue_loads = [&](int c) {
        const uint32_t stg = sb + (uint32_t)(c % NSTAGE) * STAGE_BYTES;
        const int ku = c * 16;
        {
            uint32_t doff = (uint32_t)(crow * 80 + ccb * 16);
            size_t gsrc = (eRow0 + crow) * (HH / 2) + ku + ccb * 4;
            cp16(stg + OFF_AH + doff, g_EHi + gsrc);
            cp16(stg + OFF_AL + doff, g_ELo + gsrc);
        }
        #pragma unroll
        for (int i = 0; i < 2; ++i) {
            int row = crow + i * 128;
            uint32_t doff = (uint32_t)(row * 80 + ccb * 16);
            size_t gsrc = (size_t)(n0 + row) * (HH / 2) + ku + ccb * 4;
            cp16(stg + OFF_BH + doff, g_WkHi + gsrc);
            cp16(stg + OFF_BL + doff, g_WkLo + gsrc);
        }
    };

    float C[2][8][4];
    #pragma unroll
    for (int mt = 0; mt < 2; ++mt)
        #pragma unroll
        for (int nt = 0; nt < 8; ++nt)
            #pragma unroll
            for (int r = 0; r < 4; ++r) C[mt][nt][r] = 0.f;

    issue_loads(0); CP_COMMIT();
    issue_loads(1); CP_COMMIT();

    for (int c = 0; c < NCHUNK; ++c) {
        CP_WAIT(1);              // group for chunk c complete (see tail note)
        __syncthreads();

        // refill stage (c+2)%NSTAGE — drained: last read in iter c-1.
        // Always commit (possibly empty group) so CP_WAIT(1) stays correct at tail.
        if (c + 2 < NCHUNK) issue_loads(c + 2);
        CP_COMMIT();

        const uint32_t stgA = sb + (uint32_t)(c % NSTAGE) * STAGE_BYTES + aOff;
        const uint32_t stgB = sb + (uint32_t)(c % NSTAGE) * STAGE_BYTES + OFF_BH + bOff;

        #pragma unroll
        for (int ks = 0; ks < 2; ++ks) {
            uint32_t Ah[2][4], Al[2][4];
            #pragma unroll
            for (int mt = 0; mt < 2; ++mt) {
                LDSM4(Ah[mt][0], Ah[mt][1], Ah[mt][2], Ah[mt][3],
                      stgA + (uint32_t)(ks * 32 + mt * 1280));
                LDSM4(Al[mt][0], Al[mt][1], Al[mt][2], Al[mt][3],
                      stgA + (uint32_t)(OFF_AL + ks * 32 + mt * 1280));
            }
            #pragma unroll
            for (int pair = 0; pair < 4; ++pair) {
                uint32_t Bh[4], Bl[4];
                LDSM4(Bh[0], Bh[1], Bh[2], Bh[3],
                      stgB + (uint32_t)(ks * 32 + pair * 1280));
                LDSM4(Bl[0], Bl[1], Bl[2], Bl[3],
                      stgB + (uint32_t)((OFF_BL - OFF_BH) + ks * 32 + pair * 1280));
                #pragma unroll
                for (int sub = 0; sub < 2; ++sub) {
                    const int nt = pair * 2 + sub;
                    uint32_t bh2[2] = { Bh[2 * sub], Bh[2 * sub + 1] };
                    uint32_t bl2[2] = { Bl[2 * sub], Bl[2 * sub + 1] };
                    #pragma unroll
                    for (int mt = 0; mt < 2; ++mt) {
                        mma16816(C[mt][nt], Ah[mt], bh2);   // hi*hi
                        mma16816(C[mt][nt], Al[mt], bh2);   // lo*hi
                        mma16816(C[mt][nt], Ah[mt], bl2);   // hi*lo
                    }
                }
            }
        }
    }

    // ---- epilogue: tanh(q + keys) * v, reduce over this CTA's BN columns ----
    float rs[2][2] = {{0.f, 0.f}, {0.f, 0.f}};
    #pragma unroll
    for (int mt = 0; mt < 2; ++mt)
        #pragma unroll
        for (int nt = 0; nt < 8; ++nt)
            #pragma unroll
            for (int r = 0; r < 4; ++r) {
                int col = wn * 64 + nt * 8 + tig * 2 + (r & 1);
                float e = tanhf(s_q[col] + C[mt][nt][r]) * s_v[col];
                rs[mt][r >> 1] += e;
            }

    #pragma unroll
    for (int mt = 0; mt < 2; ++mt)
        #pragma unroll
        for (int hh = 0; hh < 2; ++hh) {
            float x = rs[mt][hh];
            x += __shfl_xor_sync(0xffffffffu, x, 1);
            x += __shfl_xor_sync(0xffffffffu, x, 2);
            if (tig == 0) {
                int row = wm * 32 + mt * 16 + hh * 8 + g;
                s_red[wn * BM + row] = x;
            }
        }
    __syncthreads();

    if (tid < BM) {
        float t = s_red[tid] + s_red[BM + tid] + s_red[2 * BM + tid] + s_red[3 * BM + tid];
        g_partial[(eRow0 + tid) * NTILES + ntile] = t;
    }
}

// ---------------------------------------------------------------------------
// Masked softmax over S per batch. lengths is int32 (JAX downcast).
// Masked positions are overwritten by assignment (vv = -inf), so garbage
// partials from skipped k_attn tiles are never consumed.
// ---------------------------------------------------------------------------
__global__ void k_softmax(const int* __restrict__ lengths, float* __restrict__ out) {
    const int b = blockIdx.x;
    const int tid = threadIdx.x;      // 256 threads
    const int lane = tid & 31, wid = tid >> 5;
    int len = lengths[b];
    if (len < 1) len = 1;

    float a[8];
    float mx = -INFINITY;
    #pragma unroll
    for (int i = 0; i < 8; ++i) {
        int s = tid + i * 256;
        const float* p = &g_partial[((size_t)b * SS + s) * NTILES];
        float vv;
        if (s >= len) {
            vv = -INFINITY;               // do not touch garbage partials
        } else {
            vv = (p[0] + p[1]) + (p[2] + p[3]);
        }
        a[i] = vv;
        mx = fmaxf(mx, vv);
    }

    __shared__ float smax[8];
    __shared__ float ssum[8];

    #pragma unroll
    for (int o = 16; o > 0; o >>= 1) mx = fmaxf(mx, __shfl_xor_sync(0xffffffffu, mx, o));
    if (lane == 0) smax[wid] = mx;
    __syncthreads();
    if (wid == 0) {
        float t = (lane < 8) ? smax[lane] : -INFINITY;
        #pragma unroll
        for (int o = 4; o > 0; o >>= 1) t = fmaxf(t, __shfl_xor_sync(0xffffffffu, t, o));
        if (lane == 0) smax[0] = t;
    }
    __syncthreads();
    mx = smax[0];

    float sum = 0.f;
    #pragma unroll
    for (int i = 0; i < 8; ++i) {
        float e = expf(a[i] - mx);
        a[i] = e;
        sum += e;
    }
    #pragma unroll
    for (int o = 16; o > 0; o >>= 1) sum += __shfl_xor_sync(0xffffffffu, sum, o);
    if (lane == 0) ssum[wid] = sum;
    __syncthreads();
    if (wid == 0) {
        float t = (lane < 8) ? ssum[lane] : 0.f;
        #pragma unroll
        for (int o = 4; o > 0; o >>= 1) t += __shfl_xor_sync(0xffffffffu, t, o);
        if (lane == 0) ssum[0] = t;
    }
    __syncthreads();
    const float inv = 1.f / ssum[0];

    #pragma unroll
    for (int i = 0; i < 8; ++i) {
        int s = tid + i * 256;
        out[(size_t)b * SS + s] = a[i] * inv;
    }
}

// ---------------------------------------------------------------------------
extern "C" void kernel_launch(void* const* d_in, const int* in_sizes, int n_in,
                              void* d_out, int out_size) {
    const float* hidden  = (const float*)d_in[0];
    const float* enc     = (const float*)d_in[1];
    const int*   lengths = (const int*)d_in[2];    // int32 (JAX downcast)
    const float* Wq      = (const float*)d_in[3];
    const float* Wk      = (const float*)d_in[4];
    const float* v       = (const float*)d_in[5];
    float* out = (float*)d_out;

    cudaFuncSetAttribute(k_attn, cudaFuncAttributeMaxDynamicSharedMemorySize, SMEM_BYTES);

    k_split_wk<<<(HH * HH / 8 + 255) / 256, 256>>>(Wk);
    k_split_enc<<<(int)(((size_t)BB * SS * HH / 8 + 255) / 256), 256>>>(enc, lengths);
    k_query<<<(BB * HH + 255) / 256, 256>>>(hidden, Wq);

    dim3 grid(NTILES, STILES, BB);
    k_attn<<<grid, THREADS, SMEM_BYTES>>>(v, lengths);

    k_softmax<<<BB, 256>>>(lengths, out);
}

// round 17
// speedup vs baseline: 2.5495x; 1.8768x over previous
#include <cuda_runtime.h>
#include <cuda_bf16.h>
#include <cstdint>
#include <math.h>

// Problem constants
#define BB 32
#define SS 2048
#define HH 1024

// Tiling
#define BM 128
#define BN 128
#define KC 32                   // K elements per chunk (16 u32 of bf16x2)
#define NTILES (HH / BN)        // 8
#define STILES (SS / BM)        // 16
#define NCHUNK (HH / KC)        // 32
#define THREADS 256
#define NSTAGE 2

// Per-stage smem layout (bytes). Rows padded 64B->80B (20 u32): 16B-aligned
// for cp.async, conflict-free for ldmatrix (8 rows @ stride 20 u32 cover all banks).
#define ROW_U32 20
#define OFF_AH 0
#define OFF_AL (128 * 80)                 // 10240
#define OFF_BH (2 * 128 * 80)             // 20480
#define OFF_BL (3 * 128 * 80)             // 30720
#define STAGE_BYTES (4 * 128 * 80)        // 40960
#define SMEM_BYTES (NSTAGE * STAGE_BYTES) // 81920

// Device scratch (static; no allocations allowed)
__device__ uint32_t g_WkHi[HH * (HH / 2)];                 // bf16x2 [n][h/2]
__device__ uint32_t g_WkLo[HH * (HH / 2)];
__device__ uint32_t g_EHi[(size_t)BB * SS * (HH / 2)];     // bf16x2 [row][h/2]
__device__ uint32_t g_ELo[(size_t)BB * SS * (HH / 2)];
__device__ float    g_q[BB * HH];
__device__ float    g_partial[BB * SS * NTILES];

// ---------------------------------------------------------------------------
// Helpers
// ---------------------------------------------------------------------------
__device__ __forceinline__ uint32_t pack_bf2(__nv_bfloat16 a, __nv_bfloat16 b) {
    __nv_bfloat162 t = __halves2bfloat162(a, b);
    return *reinterpret_cast<uint32_t*>(&t);
}
__device__ __forceinline__ void split_f32(float f, __nv_bfloat16& h, __nv_bfloat16& l) {
    h = __float2bfloat16_rn(f);
    l = __float2bfloat16_rn(f - __bfloat162float(h));
}
__device__ __forceinline__ uint32_t smem_u32(const void* p) {
    uint32_t a;
    asm("{ .reg .u64 t; cvta.to.shared.u64 t, %1; cvt.u32.u64 %0, t; }" : "=r"(a) : "l"(p));
    return a;
}
__device__ __forceinline__ void cp16(uint32_t dst, const void* src) {
    asm volatile("cp.async.cg.shared.global [%0], [%1], 16;\n" :: "r"(dst), "l"(src));
}
#define CP_COMMIT() asm volatile("cp.async.commit_group;\n" ::: "memory")
#define CP_WAIT(n)  asm volatile("cp.async.wait_group %0;\n" :: "n"(n) : "memory")

#define LDSM4(r0, r1, r2, r3, addr) \
    asm volatile("ldmatrix.sync.aligned.m8n8.x4.shared.b16 {%0,%1,%2,%3}, [%4];" \
        : "=r"(r0), "=r"(r1), "=r"(r2), "=r"(r3) : "r"(addr))

__device__ __forceinline__ void mma16816(float* d, const uint32_t* a, const uint32_t* b) {
    asm volatile(
        "mma.sync.aligned.m16n8k16.row.col.f32.bf16.bf16.f32 "
        "{%0,%1,%2,%3}, {%4,%5,%6,%7}, {%8,%9}, {%0,%1,%2,%3};\n"
        : "+f"(d[0]), "+f"(d[1]), "+f"(d[2]), "+f"(d[3])
        : "r"(a[0]), "r"(a[1]), "r"(a[2]), "r"(a[3]), "r"(b[0]), "r"(b[1]));
}

// ---------------------------------------------------------------------------
// Prep: split Wk into bf16 hi/lo (K-major rows of 1024)
// ---------------------------------------------------------------------------
__global__ void k_split_wk(const float* __restrict__ Wk) {
    int i8 = blockIdx.x * blockDim.x + threadIdx.x;   // unit of 8 floats
    if (i8 >= HH * HH / 8) return;
    const float4 f0 = *reinterpret_cast<const float4*>(Wk + (size_t)i8 * 8);
    const float4 f1 = *reinterpret_cast<const float4*>(Wk + (size_t)i8 * 8 + 4);
    __nv_bfloat16 h[8], l[8];
    split_f32(f0.x, h[0], l[0]); split_f32(f0.y, h[1], l[1]);
    split_f32(f0.z, h[2], l[2]); split_f32(f0.w, h[3], l[3]);
    split_f32(f1.x, h[4], l[4]); split_f32(f1.y, h[5], l[5]);
    split_f32(f1.z, h[6], l[6]); split_f32(f1.w, h[7], l[7]);
    uint4 hi = { pack_bf2(h[0], h[1]), pack_bf2(h[2], h[3]), pack_bf2(h[4], h[5]), pack_bf2(h[6], h[7]) };
    uint4 lo = { pack_bf2(l[0], l[1]), pack_bf2(l[2], l[3]), pack_bf2(l[4], l[5]), pack_bf2(l[6], l[7]) };
    reinterpret_cast<uint4*>(g_WkHi)[i8] = hi;
    reinterpret_cast<uint4*>(g_WkLo)[i8] = lo;
}

// ---------------------------------------------------------------------------
// Prep: split encoder_outputs into bf16 hi/lo (length-masked).
// ---------------------------------------------------------------------------
__global__ void k_split_enc(const float* __restrict__ enc, const int* __restrict__ lengths) {
    size_t i8 = (size_t)blockIdx.x * blockDim.x + threadIdx.x;   // unit of 8 floats
    if (i8 >= (size_t)BB * SS * HH / 8) return;
    const int row = (int)(i8 / (HH / 8));
    const int b = row / SS;
    const int s = row % SS;
    int len = lengths[b];
    if (len < 1) len = 1;
    const int lim = (len + BM - 1) & ~(BM - 1);   // round up to stile granularity
    if (s >= lim) return;                          // dead row: skip read+write
    const float4 f0 = *reinterpret_cast<const float4*>(enc + i8 * 8);
    const float4 f1 = *reinterpret_cast<const float4*>(enc + i8 * 8 + 4);
    __nv_bfloat16 h[8], l[8];
    split_f32(f0.x, h[0], l[0]); split_f32(f0.y, h[1], l[1]);
    split_f32(f0.z, h[2], l[2]); split_f32(f0.w, h[3], l[3]);
    split_f32(f1.x, h[4], l[4]); split_f32(f1.y, h[5], l[5]);
    split_f32(f1.z, h[6], l[6]); split_f32(f1.w, h[7], l[7]);
    uint4 hi = { pack_bf2(h[0], h[1]), pack_bf2(h[2], h[3]), pack_bf2(h[4], h[5]), pack_bf2(h[6], h[7]) };
    uint4 lo = { pack_bf2(l[0], l[1]), pack_bf2(l[2], l[3]), pack_bf2(l[4], l[5]), pack_bf2(l[6], l[7]) };
    reinterpret_cast<uint4*>(g_EHi)[i8] = hi;
    reinterpret_cast<uint4*>(g_ELo)[i8] = lo;
}

// ---------------------------------------------------------------------------
// Prep: q[b][n] = hidden[b] . Wq[n] — one warp per output, float4 loads,
// shuffle reduction. Replaces the latency-bound scalar version.
// ---------------------------------------------------------------------------
__global__ void k_query(const float* __restrict__ hidden, const float* __restrict__ Wq) {
    const int w = (blockIdx.x * blockDim.x + threadIdx.x) >> 5;   // warp id = output idx
    const int lane = threadIdx.x & 31;
    if (w >= BB * HH) return;
    const int b = w >> 10;
    const int n = w & 1023;
    const float4* hp = reinterpret_cast<const float4*>(hidden + (size_t)b * HH);
    const float4* wp = reinterpret_cast<const float4*>(Wq + (size_t)n * HH);
    float acc = 0.f;
    #pragma unroll
    for (int i = 0; i < 8; ++i) {
        float4 h4 = hp[lane + i * 32];
        float4 w4 = wp[lane + i * 32];
        acc = fmaf(h4.x, w4.x, acc);
        acc = fmaf(h4.y, w4.y, acc);
        acc = fmaf(h4.z, w4.z, acc);
        acc = fmaf(h4.w, w4.w, acc);
    }
    #pragma unroll
    for (int o = 16; o > 0; o >>= 1) acc += __shfl_xor_sync(0xffffffffu, acc, o);
    if (lane == 0) g_q[w] = acc;
}

// ---------------------------------------------------------------------------
// Main fused kernel: bf16x3 mma.sync GEMM + tanh(q+keys)*v row reduction.
// BM=128 x BN=128, 256 threads, 2 CTAs/SM (cross-CTA bubble filling),
// 2-stage cp.async, ldmatrix fragments, length-aware early exit.
// Grid (NTILES=8, STILES, BB), ntile fastest for L2 reuse of E tiles.
// ---------------------------------------------------------------------------
__global__ __launch_bounds__(THREADS, 2)
void k_attn(const float* __restrict__ v, const int* __restrict__ lengths) {
    extern __shared__ uint32_t smem[];
    __shared__ float s_q[BN];
    __shared__ float s_v[BN];
    __shared__ float s_red[2 * BM];

    const uint32_t sb = smem_u32(smem);

    const int tid = threadIdx.x;
    const int ntile = blockIdx.x;
    const int stile = blockIdx.y;
    const int b = blockIdx.z;

    // Length-aware early exit (uniform per-CTA, before any barrier).
    if (stile * BM >= lengths[b]) return;

    const int n0 = ntile * BN;
    const size_t eRow0 = (size_t)b * SS + (size_t)stile * BM;

    if (tid < BN) {
        s_q[tid] = g_q[b * HH + n0 + tid];
        s_v[tid] = v[n0 + tid];
    }

    const int lane = tid & 31;
    const int wid  = tid >> 5;       // 8 warps
    const int g    = lane >> 2;
    const int tig  = lane & 3;
    const int wm   = wid & 3;        // 4 warps along M (rows of 32)
    const int wn   = wid >> 2;       // 2 warps along N (cols of 64)

    // ldmatrix per-lane byte offsets within stage
    const int l7 = lane & 7;
    const uint32_t aOff = (uint32_t)((wm * 32 + l7 + ((lane >> 3) & 1) * 8) * 80
                                     + ((lane >> 4) & 1) * 16);
    const uint32_t bOff = (uint32_t)((wn * 64 + l7 + (lane >> 4) * 8) * 80
                                     + ((lane >> 3) & 1) * 16);

    // cp.async: copy chunk c into stage c%NSTAGE. 256 threads:
    // each thread does 2 rows per array (A 128 rows, B 128 rows).
    const int crow = tid >> 2;       // 0..63
    const int ccb  = tid & 3;        // 16B block within 64B row chunk
    auto issue_loads = [&](int c) {
        const uint32_t stg = sb + (uint32_t)(c % NSTAGE) * STAGE_BYTES;
        const int ku = c * 16;
        #pragma unroll
        for (int i = 0; i < 2; ++i) {
            int row = crow + i * 64;
            uint32_t doff = (uint32_t)(row * 80 + ccb * 16);
            size_t gA = (eRow0 + row) * (HH / 2) + ku + ccb * 4;
            size_t gB = (size_t)(n0 + row) * (HH / 2) + ku + ccb * 4;
            cp16(stg + OFF_AH + doff, g_EHi + gA);
            cp16(stg + OFF_AL + doff, g_ELo + gA);
            cp16(stg + OFF_BH + doff, g_WkHi + gB);
            cp16(stg + OFF_BL + doff, g_WkLo + gB);
        }
    };

    float C[2][8][4];
    #pragma unroll
    for (int mt = 0; mt < 2; ++mt)
        #pragma unroll
        for (int nt = 0; nt < 8; ++nt)
            #pragma unroll
            for (int r = 0; r < 4; ++r) C[mt][nt][r] = 0.f;

    issue_loads(0); CP_COMMIT();
    issue_loads(1); CP_COMMIT();

    for (int c = 0; c < NCHUNK; ++c) {
        CP_WAIT(1);              // chunk c group retired
        __syncthreads();

        const uint32_t stgA = sb + (uint32_t)(c % NSTAGE) * STAGE_BYTES + aOff;
        const uint32_t stgB = sb + (uint32_t)(c % NSTAGE) * STAGE_BYTES + OFF_BH + bOff;

        #pragma unroll
        for (int ks = 0; ks < 2; ++ks) {
            uint32_t Ah[2][4], Al[2][4];
            #pragma unroll
            for (int mt = 0; mt < 2; ++mt) {
                LDSM4(Ah[mt][0], Ah[mt][1], Ah[mt][2], Ah[mt][3],
                      stgA + (uint32_t)(ks * 32 + mt * 1280));
                LDSM4(Al[mt][0], Al[mt][1], Al[mt][2], Al[mt][3],
                      stgA + (uint32_t)(OFF_AL + ks * 32 + mt * 1280));
            }
            #pragma unroll
            for (int pair = 0; pair < 4; ++pair) {
                uint32_t Bh[4], Bl[4];
                LDSM4(Bh[0], Bh[1], Bh[2], Bh[3],
                      stgB + (uint32_t)(ks * 32 + pair * 1280));
                LDSM4(Bl[0], Bl[1], Bl[2], Bl[3],
                      stgB + (uint32_t)((OFF_BL - OFF_BH) + ks * 32 + pair * 1280));
                #pragma unroll
                for (int sub = 0; sub < 2; ++sub) {
                    const int nt = pair * 2 + sub;
                    uint32_t bh2[2] = { Bh[2 * sub], Bh[2 * sub + 1] };
                    uint32_t bl2[2] = { Bl[2 * sub], Bl[2 * sub + 1] };
                    #pragma unroll
                    for (int mt = 0; mt < 2; ++mt) {
                        mma16816(C[mt][nt], Ah[mt], bh2);   // hi*hi
                        mma16816(C[mt][nt], Al[mt], bh2);   // lo*hi
                        mma16816(C[mt][nt], Ah[mt], bl2);   // hi*lo
                    }
                }
            }
        }

        // Stage (c%NSTAGE) is re-filled for chunk c+2 only after all warps
        // finished reading it (second barrier). Other-CTA work hides the wait.
        __syncthreads();
        if (c + 2 < NCHUNK) issue_loads(c + 2);
        CP_COMMIT();             // always commit (possibly empty) for CP_WAIT(1)
    }

    // ---- epilogue: tanh(q + keys) * v, reduce over this CTA's BN columns ----
    float rs[2][2] = {{0.f, 0.f}, {0.f, 0.f}};
    #pragma unroll
    for (int mt = 0; mt < 2; ++mt)
        #pragma unroll
        for (int nt = 0; nt < 8; ++nt)
            #pragma unroll
            for (int r = 0; r < 4; ++r) {
                int col = wn * 64 + nt * 8 + tig * 2 + (r & 1);
                float e = tanhf(s_q[col] + C[mt][nt][r]) * s_v[col];
                rs[mt][r >> 1] += e;
            }

    #pragma unroll
    for (int mt = 0; mt < 2; ++mt)
        #pragma unroll
        for (int hh = 0; hh < 2; ++hh) {
            float x = rs[mt][hh];
            x += __shfl_xor_sync(0xffffffffu, x, 1);
            x += __shfl_xor_sync(0xffffffffu, x, 2);
            if (tig == 0) {
                int row = wm * 32 + mt * 16 + hh * 8 + g;
                s_red[wn * BM + row] = x;
            }
        }
    __syncthreads();

    if (tid < BM) {
        float t = s_red[tid] + s_red[BM + tid];
        g_partial[(eRow0 + tid) * NTILES + ntile] = t;
    }
}

// ---------------------------------------------------------------------------
// Masked softmax over S per batch. lengths is int32 (JAX downcast).
// ---------------------------------------------------------------------------
__global__ void k_softmax(const int* __restrict__ lengths, float* __restrict__ out) {
    const int b = blockIdx.x;
    const int tid = threadIdx.x;      // 256 threads
    const int lane = tid & 31, wid = tid >> 5;
    int len = lengths[b];
    if (len < 1) len = 1;

    float a[8];
    float mx = -INFINITY;
    #pragma unroll
    for (int i = 0; i < 8; ++i) {
        int s = tid + i * 256;
        const float* p = &g_partial[((size_t)b * SS + s) * NTILES];
        float vv;
        if (s >= len) {
            vv = -INFINITY;               // do not touch garbage partials
        } else {
            vv = ((p[0] + p[1]) + (p[2] + p[3])) + ((p[4] + p[5]) + (p[6] + p[7]));
        }
        a[i] = vv;
        mx = fmaxf(mx, vv);
    }

    __shared__ float smax[8];
    __shared__ float ssum[8];

    #pragma unroll
    for (int o = 16; o > 0; o >>= 1) mx = fmaxf(mx, __shfl_xor_sync(0xffffffffu, mx, o));
    if (lane == 0) smax[wid] = mx;
    __syncthreads();
    if (wid == 0) {
        float t = (lane < 8) ? smax[lane] : -INFINITY;
        #pragma unroll
        for (int o = 4; o > 0; o >>= 1) t = fmaxf(t, __shfl_xor_sync(0xffffffffu, t, o));
        if (lane == 0) smax[0] = t;
    }
    __syncthreads();
    mx = smax[0];

    float sum = 0.f;
    #pragma unroll
    for (int i = 0; i < 8; ++i) {
        float e = expf(a[i] - mx);
        a[i] = e;
        sum += e;
    }
    #pragma unroll
    for (int o = 16; o > 0; o >>= 1) sum += __shfl_xor_sync(0xffffffffu, sum, o);
    if (lane == 0) ssum[wid] = sum;
    __syncthreads();
    if (wid == 0) {
        float t = (lane < 8) ? ssum[lane] : 0.f;
        #pragma unroll
        for (int o = 4; o > 0; o >>= 1) t += __shfl_xor_sync(0xffffffffu, t, o);
        if (lane == 0) ssum[0] = t;
    }
    __syncthreads();
    const float inv = 1.f / ssum[0];

    #pragma unroll
    for (int i = 0; i < 8; ++i) {
        int s = tid + i * 256;
        out[(size_t)b * SS + s] = a[i] * inv;
    }
}

// ---------------------------------------------------------------------------
extern "C" void kernel_launch(void* const* d_in, const int* in_sizes, int n_in,
                              void* d_out, int out_size) {
    const float* hidden  = (const float*)d_in[0];
    const float* enc     = (const float*)d_in[1];
    const int*   lengths = (const int*)d_in[2];    // int32 (JAX downcast)
    const float* Wq      = (const float*)d_in[3];
    const float* Wk      = (const float*)d_in[4];
    const float* v       = (const float*)d_in[5];
    float* out = (float*)d_out;

    cudaFuncSetAttribute(k_attn, cudaFuncAttributeMaxDynamicSharedMemorySize, SMEM_BYTES);

    k_split_wk<<<(HH * HH / 8 + 255) / 256, 256>>>(Wk);
    k_split_enc<<<(int)(((size_t)BB * SS * HH / 8 + 255) / 256), 256>>>(enc, lengths);
    k_query<<<(BB * HH * 32 + 255) / 256, 256>>>(hidden, Wq);

    dim3 grid(NTILES, STILES, BB);
    k_attn<<<grid, THREADS, SMEM_BYTES>>>(v, lengths);

    k_softmax<<<BB, 256>>>(lengths, out);
}